// round 4
// baseline (speedup 1.0000x reference)
#include <cuda_runtime.h>

// LorenzPINN: per-row forward + JVP of a 1->20->20->20->20->3 tanh MLP + Lorenz
// residuals. fp32, packed f32x2 FMA (value+tangent share each weight).
// R3: 2 rows per thread (weight-broadcast LDS bytes amortized 2x; crossbar was
//     the binder at 90% L1) + split even/odd accumulators for 4-way chain ILP.

#define W 20
typedef unsigned long long u64;

__device__ __forceinline__ u64 pack2(float lo, float hi) {
    u64 r; asm("mov.b64 %0,{%1,%2};" : "=l"(r) : "f"(lo), "f"(hi)); return r;
}
__device__ __forceinline__ void unpack2(u64 v, float& lo, float& hi) {
    asm("mov.b64 {%0,%1},%2;" : "=f"(lo), "=f"(hi) : "l"(v));
}
__device__ __forceinline__ u64 ffma2(u64 a, u64 b, u64 c) {
    u64 d; asm("fma.rn.f32x2 %0,%1,%2,%3;" : "=l"(d) : "l"(a), "l"(b), "l"(c)); return d;
}
__device__ __forceinline__ u64 fadd2(u64 a, u64 b) {
    u64 d; asm("add.rn.f32x2 %0,%1,%2;" : "=l"(d) : "l"(a), "l"(b)); return d;
}

// tanh(x) = 1 - 2/(e^{2x}+1) via MUFU EX2 + RCP. Saturates correctly at +-inf.
__device__ __forceinline__ float fast_tanh(float x) {
    float e;
    asm("ex2.approx.f32 %0, %1;" : "=f"(e) : "f"(x * 2.885390081777927f)); // 2*log2(e)
    float r;
    asm("rcp.approx.f32 %0, %1;" : "=f"(r) : "f"(e + 1.0f));
    return fmaf(-2.0f, r, 1.0f);
}

// One hidden layer for TWO rows. Weights (w,w)-duplicated in shared, biases
// pre-packed (b,0). Each LDS.128 (two weight pairs) feeds 4 FFMA2 (2 rows).
// Split even/odd accumulators give 4 independent chains per warp.
__device__ __forceinline__ void layer2(u64 (&h0)[W], u64 (&h1)[W],
                                       const u64* __restrict__ sw,
                                       const u64* __restrict__ sbp) {
    u64 n0[W], n1[W];
#pragma unroll
    for (int j = 0; j < W; j++) {
        const ulonglong2* row = reinterpret_cast<const ulonglong2*>(sw + j * W);
        u64 bj = sbp[j];                       // (b, 0)
        u64 a0 = bj, c0 = pack2(0.0f, 0.0f);
        u64 a1 = bj, c1 = pack2(0.0f, 0.0f);
#pragma unroll
        for (int kk = 0; kk < W / 2; kk++) {
            ulonglong2 wp = row[kk];
            a0 = ffma2(h0[2 * kk + 0], wp.x, a0);
            c0 = ffma2(h0[2 * kk + 1], wp.y, c0);
            a1 = ffma2(h1[2 * kk + 0], wp.x, a1);
            c1 = ffma2(h1[2 * kk + 1], wp.y, c1);
        }
        a0 = fadd2(a0, c0);
        a1 = fadd2(a1, c1);
        float z, dz, th, s;
        unpack2(a0, z, dz);
        th = fast_tanh(z); s = th * dz;
        n0[j] = pack2(th, fmaf(-th, s, dz));   // (th, (1-th^2)*dz)
        unpack2(a1, z, dz);
        th = fast_tanh(z); s = th * dz;
        n1[j] = pack2(th, fmaf(-th, s, dz));
    }
#pragma unroll
    for (int j = 0; j < W; j++) { h0[j] = n0[j]; h1[j] = n1[j]; }
}

__global__ __launch_bounds__(128)
void lorenz_pinn_kernel(const float* __restrict__ t,
                        const float* __restrict__ W1, const float* __restrict__ b1,
                        const float* __restrict__ W2, const float* __restrict__ b2,
                        const float* __restrict__ W3, const float* __restrict__ b3,
                        const float* __restrict__ W4, const float* __restrict__ b4,
                        const float* __restrict__ Wo, const float* __restrict__ bo,
                        const float* __restrict__ c1p, const float* __restrict__ c2p,
                        const float* __restrict__ c3p,
                        float* __restrict__ out, int n) {
    __shared__ __align__(16) u64 sW2[W * W];
    __shared__ __align__(16) u64 sW3[W * W];
    __shared__ __align__(16) u64 sW4[W * W];
    __shared__ __align__(16) u64 sWo[3 * W];
    __shared__ u64 sb2p[W], sb3p[W], sb4p[W];
    __shared__ float sW1[W], sb1[W], sbo[4];

    for (int idx = threadIdx.x; idx < W * W; idx += blockDim.x) {
        int j = idx / W, k = idx % W;
        float w2 = W2[k * W + j]; sW2[idx] = pack2(w2, w2);
        float w3 = W3[k * W + j]; sW3[idx] = pack2(w3, w3);
        float w4 = W4[k * W + j]; sW4[idx] = pack2(w4, w4);
    }
    if (threadIdx.x < 3 * W) {
        int c = threadIdx.x / W, k = threadIdx.x % W;
        float w = Wo[k * 3 + c];
        sWo[threadIdx.x] = pack2(w, w);
    }
    if (threadIdx.x < W) {
        sW1[threadIdx.x] = W1[threadIdx.x];
        sb1[threadIdx.x] = b1[threadIdx.x];
        sb2p[threadIdx.x] = pack2(b2[threadIdx.x], 0.0f);
        sb3p[threadIdx.x] = pack2(b3[threadIdx.x], 0.0f);
        sb4p[threadIdx.x] = pack2(b4[threadIdx.x], 0.0f);
    }
    if (threadIdx.x < 3) sbo[threadIdx.x] = bo[threadIdx.x];
    __syncthreads();

    int i0 = blockIdx.x * 256 + threadIdx.x;   // two coalesced row groups
    int i1 = i0 + 128;
    if (i0 >= n) return;
    bool has1 = (i1 < n);

    float tv0 = t[i0];
    float tv1 = has1 ? t[i1] : 0.0f;
    float C1 = __ldg(c1p), C2 = __ldg(c2p), C3 = __ldg(c3p);

    // Layer 1: pre = t*W1 + b1, dpre = W1 (tangent of t is 1).
    u64 h0[W], h1[W];
#pragma unroll
    for (int j = 0; j < W; j++) {
        float w = sW1[j], b = sb1[j];
        float th0 = fast_tanh(fmaf(tv0, w, b));
        h0[j] = pack2(th0, fmaf(-th0, th0 * w, w));
        float th1 = fast_tanh(fmaf(tv1, w, b));
        h1[j] = pack2(th1, fmaf(-th1, th1 * w, w));
    }

    layer2(h0, h1, sW2, sb2p);
    layer2(h0, h1, sW3, sb3p);
    layer2(h0, h1, sW4, sb4p);

    // Output head (3 units, no activation) for both rows.
    float o0[3], d0[3], o1[3], d1[3];
#pragma unroll
    for (int c = 0; c < 3; c++) {
        const ulonglong2* row = reinterpret_cast<const ulonglong2*>(sWo + c * W);
        u64 bc = pack2(sbo[c], 0.0f);
        u64 a0 = bc, e0 = pack2(0.0f, 0.0f);
        u64 a1 = bc, e1 = pack2(0.0f, 0.0f);
#pragma unroll
        for (int kk = 0; kk < W / 2; kk++) {
            ulonglong2 wp = row[kk];
            a0 = ffma2(h0[2 * kk + 0], wp.x, a0);
            e0 = ffma2(h0[2 * kk + 1], wp.y, e0);
            a1 = ffma2(h1[2 * kk + 0], wp.x, a1);
            e1 = ffma2(h1[2 * kk + 1], wp.y, e1);
        }
        unpack2(fadd2(a0, e0), o0[c], d0[c]);
        unpack2(fadd2(a1, e1), o1[c], d1[c]);
    }

    {
        float x = o0[0], y = o0[1], z = o0[2];
        float fx = d0[0] - C1 * (y - x);
        float fy = d0[1] - x * (C2 - z) + y;
        float fz = d0[2] - x * y + C3 * z;
        float* po = out + (size_t)i0 * 6;
        po[0] = x; po[1] = y; po[2] = z; po[3] = fx; po[4] = fy; po[5] = fz;
    }
    if (has1) {
        float x = o1[0], y = o1[1], z = o1[2];
        float fx = d1[0] - C1 * (y - x);
        float fy = d1[1] - x * (C2 - z) + y;
        float fz = d1[2] - x * y + C3 * z;
        float* po = out + (size_t)i1 * 6;
        po[0] = x; po[1] = y; po[2] = z; po[3] = fx; po[4] = fy; po[5] = fz;
    }
}

extern "C" void kernel_launch(void* const* d_in, const int* in_sizes, int n_in,
                              void* d_out, int out_size) {
    const float* t  = (const float*)d_in[0];
    const float* W1 = (const float*)d_in[1];
    const float* b1 = (const float*)d_in[2];
    const float* W2 = (const float*)d_in[3];
    const float* b2 = (const float*)d_in[4];
    const float* W3 = (const float*)d_in[5];
    const float* b3 = (const float*)d_in[6];
    const float* W4 = (const float*)d_in[7];
    const float* b4 = (const float*)d_in[8];
    const float* Wo = (const float*)d_in[9];
    const float* bo = (const float*)d_in[10];
    const float* c1 = (const float*)d_in[11];
    const float* c2 = (const float*)d_in[12];
    const float* c3 = (const float*)d_in[13];
    float* out = (float*)d_out;
    int n = in_sizes[0];
    int blocks = (n + 255) / 256;   // 128 threads x 2 rows each
    lorenz_pinn_kernel<<<blocks, 128>>>(t, W1, b1, W2, b2, W3, b3, W4, b4,
                                        Wo, bo, c1, c2, c3, out, n);
}

// round 5
// speedup vs baseline: 1.0152x; 1.0152x over previous
#include <cuda_runtime.h>

// LorenzPINN: per-row forward + JVP of a 1->20->20->20->20->3 tanh MLP + Lorenz
// residuals. fp32, packed f32x2 FMA (value+tangent share each weight).
// R3: 2 rows per thread (weight-broadcast LDS bytes amortized 2x; crossbar was
//     the binder at 90% L1) + split even/odd accumulators for 4-way chain ILP.

#define W 20
typedef unsigned long long u64;

__device__ __forceinline__ u64 pack2(float lo, float hi) {
    u64 r; asm("mov.b64 %0,{%1,%2};" : "=l"(r) : "f"(lo), "f"(hi)); return r;
}
__device__ __forceinline__ void unpack2(u64 v, float& lo, float& hi) {
    asm("mov.b64 {%0,%1},%2;" : "=f"(lo), "=f"(hi) : "l"(v));
}
__device__ __forceinline__ u64 ffma2(u64 a, u64 b, u64 c) {
    u64 d; asm("fma.rn.f32x2 %0,%1,%2,%3;" : "=l"(d) : "l"(a), "l"(b), "l"(c)); return d;
}
__device__ __forceinline__ u64 fadd2(u64 a, u64 b) {
    u64 d; asm("add.rn.f32x2 %0,%1,%2;" : "=l"(d) : "l"(a), "l"(b)); return d;
}

// tanh(x) = 1 - 2/(e^{2x}+1) via MUFU EX2 + RCP. Saturates correctly at +-inf.
__device__ __forceinline__ float fast_tanh(float x) {
    float e;
    asm("ex2.approx.f32 %0, %1;" : "=f"(e) : "f"(x * 2.885390081777927f)); // 2*log2(e)
    float r;
    asm("rcp.approx.f32 %0, %1;" : "=f"(r) : "f"(e + 1.0f));
    return fmaf(-2.0f, r, 1.0f);
}

// One hidden layer for TWO rows. Weights (w,w)-duplicated in shared, biases
// pre-packed (b,0). Each LDS.128 (two weight pairs) feeds 4 FFMA2 (2 rows).
// Split even/odd accumulators give 4 independent chains per warp.
__device__ __forceinline__ void layer2(u64 (&h0)[W], u64 (&h1)[W],
                                       const u64* __restrict__ sw,
                                       const u64* __restrict__ sbp) {
    u64 n0[W], n1[W];
#pragma unroll
    for (int j = 0; j < W; j++) {
        const ulonglong2* row = reinterpret_cast<const ulonglong2*>(sw + j * W);
        u64 bj = sbp[j];                       // (b, 0)
        u64 a0 = bj, c0 = pack2(0.0f, 0.0f);
        u64 a1 = bj, c1 = pack2(0.0f, 0.0f);
#pragma unroll
        for (int kk = 0; kk < W / 2; kk++) {
            ulonglong2 wp = row[kk];
            a0 = ffma2(h0[2 * kk + 0], wp.x, a0);
            c0 = ffma2(h0[2 * kk + 1], wp.y, c0);
            a1 = ffma2(h1[2 * kk + 0], wp.x, a1);
            c1 = ffma2(h1[2 * kk + 1], wp.y, c1);
        }
        a0 = fadd2(a0, c0);
        a1 = fadd2(a1, c1);
        float z, dz, th, s;
        unpack2(a0, z, dz);
        th = fast_tanh(z); s = th * dz;
        n0[j] = pack2(th, fmaf(-th, s, dz));   // (th, (1-th^2)*dz)
        unpack2(a1, z, dz);
        th = fast_tanh(z); s = th * dz;
        n1[j] = pack2(th, fmaf(-th, s, dz));
    }
#pragma unroll
    for (int j = 0; j < W; j++) { h0[j] = n0[j]; h1[j] = n1[j]; }
}

__global__ __launch_bounds__(128)
void lorenz_pinn_kernel(const float* __restrict__ t,
                        const float* __restrict__ W1, const float* __restrict__ b1,
                        const float* __restrict__ W2, const float* __restrict__ b2,
                        const float* __restrict__ W3, const float* __restrict__ b3,
                        const float* __restrict__ W4, const float* __restrict__ b4,
                        const float* __restrict__ Wo, const float* __restrict__ bo,
                        const float* __restrict__ c1p, const float* __restrict__ c2p,
                        const float* __restrict__ c3p,
                        float* __restrict__ out, int n) {
    __shared__ __align__(16) u64 sW2[W * W];
    __shared__ __align__(16) u64 sW3[W * W];
    __shared__ __align__(16) u64 sW4[W * W];
    __shared__ __align__(16) u64 sWo[3 * W];
    __shared__ u64 sb2p[W], sb3p[W], sb4p[W];
    __shared__ float sW1[W], sb1[W], sbo[4];

    for (int idx = threadIdx.x; idx < W * W; idx += blockDim.x) {
        int j = idx / W, k = idx % W;
        float w2 = W2[k * W + j]; sW2[idx] = pack2(w2, w2);
        float w3 = W3[k * W + j]; sW3[idx] = pack2(w3, w3);
        float w4 = W4[k * W + j]; sW4[idx] = pack2(w4, w4);
    }
    if (threadIdx.x < 3 * W) {
        int c = threadIdx.x / W, k = threadIdx.x % W;
        float w = Wo[k * 3 + c];
        sWo[threadIdx.x] = pack2(w, w);
    }
    if (threadIdx.x < W) {
        sW1[threadIdx.x] = W1[threadIdx.x];
        sb1[threadIdx.x] = b1[threadIdx.x];
        sb2p[threadIdx.x] = pack2(b2[threadIdx.x], 0.0f);
        sb3p[threadIdx.x] = pack2(b3[threadIdx.x], 0.0f);
        sb4p[threadIdx.x] = pack2(b4[threadIdx.x], 0.0f);
    }
    if (threadIdx.x < 3) sbo[threadIdx.x] = bo[threadIdx.x];
    __syncthreads();

    int i0 = blockIdx.x * 256 + threadIdx.x;   // two coalesced row groups
    int i1 = i0 + 128;
    if (i0 >= n) return;
    bool has1 = (i1 < n);

    float tv0 = t[i0];
    float tv1 = has1 ? t[i1] : 0.0f;
    float C1 = __ldg(c1p), C2 = __ldg(c2p), C3 = __ldg(c3p);

    // Layer 1: pre = t*W1 + b1, dpre = W1 (tangent of t is 1).
    u64 h0[W], h1[W];
#pragma unroll
    for (int j = 0; j < W; j++) {
        float w = sW1[j], b = sb1[j];
        float th0 = fast_tanh(fmaf(tv0, w, b));
        h0[j] = pack2(th0, fmaf(-th0, th0 * w, w));
        float th1 = fast_tanh(fmaf(tv1, w, b));
        h1[j] = pack2(th1, fmaf(-th1, th1 * w, w));
    }

    layer2(h0, h1, sW2, sb2p);
    layer2(h0, h1, sW3, sb3p);
    layer2(h0, h1, sW4, sb4p);

    // Output head (3 units, no activation) for both rows.
    float o0[3], d0[3], o1[3], d1[3];
#pragma unroll
    for (int c = 0; c < 3; c++) {
        const ulonglong2* row = reinterpret_cast<const ulonglong2*>(sWo + c * W);
        u64 bc = pack2(sbo[c], 0.0f);
        u64 a0 = bc, e0 = pack2(0.0f, 0.0f);
        u64 a1 = bc, e1 = pack2(0.0f, 0.0f);
#pragma unroll
        for (int kk = 0; kk < W / 2; kk++) {
            ulonglong2 wp = row[kk];
            a0 = ffma2(h0[2 * kk + 0], wp.x, a0);
            e0 = ffma2(h0[2 * kk + 1], wp.y, e0);
            a1 = ffma2(h1[2 * kk + 0], wp.x, a1);
            e1 = ffma2(h1[2 * kk + 1], wp.y, e1);
        }
        unpack2(fadd2(a0, e0), o0[c], d0[c]);
        unpack2(fadd2(a1, e1), o1[c], d1[c]);
    }

    {
        float x = o0[0], y = o0[1], z = o0[2];
        float fx = d0[0] - C1 * (y - x);
        float fy = d0[1] - x * (C2 - z) + y;
        float fz = d0[2] - x * y + C3 * z;
        float* po = out + (size_t)i0 * 6;
        po[0] = x; po[1] = y; po[2] = z; po[3] = fx; po[4] = fy; po[5] = fz;
    }
    if (has1) {
        float x = o1[0], y = o1[1], z = o1[2];
        float fx = d1[0] - C1 * (y - x);
        float fy = d1[1] - x * (C2 - z) + y;
        float fz = d1[2] - x * y + C3 * z;
        float* po = out + (size_t)i1 * 6;
        po[0] = x; po[1] = y; po[2] = z; po[3] = fx; po[4] = fy; po[5] = fz;
    }
}

extern "C" void kernel_launch(void* const* d_in, const int* in_sizes, int n_in,
                              void* d_out, int out_size) {
    const float* t  = (const float*)d_in[0];
    const float* W1 = (const float*)d_in[1];
    const float* b1 = (const float*)d_in[2];
    const float* W2 = (const float*)d_in[3];
    const float* b2 = (const float*)d_in[4];
    const float* W3 = (const float*)d_in[5];
    const float* b3 = (const float*)d_in[6];
    const float* W4 = (const float*)d_in[7];
    const float* b4 = (const float*)d_in[8];
    const float* Wo = (const float*)d_in[9];
    const float* bo = (const float*)d_in[10];
    const float* c1 = (const float*)d_in[11];
    const float* c2 = (const float*)d_in[12];
    const float* c3 = (const float*)d_in[13];
    float* out = (float*)d_out;
    int n = in_sizes[0];
    int blocks = (n + 255) / 256;   // 128 threads x 2 rows each
    lorenz_pinn_kernel<<<blocks, 128>>>(t, W1, b1, W2, b2, W3, b3, W4, b4,
                                        Wo, bo, c1, c2, c3, out, n);
}

// round 6
// speedup vs baseline: 1.1621x; 1.1447x over previous
#include <cuda_runtime.h>

// LorenzPINN: per-row forward + JVP of a 1->20->20->20->20->3 tanh MLP + Lorenz
// residuals. fp32.
// R4: pack f32x2 along the K dimension: hv[kk]=(h[2kk],h[2kk+1]),
//     dv[kk]=(dh[2kk],dh[2kk+1]); weights stored UNduplicated as pairs
//     (w[2kk][j],w[2kk+1][j]) -> 4B/weight in smem (half of R1's broadcast
//     bytes), 1 row/thread so registers stay ~R1 level (occupancy restored).

#define W  20
#define KP 10          // k-pairs per row
#define RS 12          // padded row stride in u64 (96B, 16B-aligned rows)
typedef unsigned long long u64;

__device__ __forceinline__ u64 pack2(float lo, float hi) {
    u64 r; asm("mov.b64 %0,{%1,%2};" : "=l"(r) : "f"(lo), "f"(hi)); return r;
}
__device__ __forceinline__ void unpack2(u64 v, float& lo, float& hi) {
    asm("mov.b64 {%0,%1},%2;" : "=f"(lo), "=f"(hi) : "l"(v));
}
__device__ __forceinline__ u64 ffma2(u64 a, u64 b, u64 c) {
    u64 d; asm("fma.rn.f32x2 %0,%1,%2,%3;" : "=l"(d) : "l"(a), "l"(b), "l"(c)); return d;
}

// tanh(x) = 1 - 2/(e^{2x}+1) via MUFU EX2 + RCP. Saturates correctly at +-inf.
__device__ __forceinline__ float fast_tanh(float x) {
    float e;
    asm("ex2.approx.f32 %0, %1;" : "=f"(e) : "f"(x * 2.885390081777927f)); // 2*log2(e)
    float r;
    asm("rcp.approx.f32 %0, %1;" : "=f"(r) : "f"(e + 1.0f));
    return fmaf(-2.0f, r, 1.0f);
}

// One hidden layer. Value and tangent accumulate in packed even/odd-k chains;
// one horizontal add each at the end. Weights via LDS.128 (2 pairs / 4 FFMA2).
__device__ __forceinline__ void layer(u64 (&hv)[KP], u64 (&dv)[KP],
                                      const u64* __restrict__ sw,
                                      const u64* __restrict__ sbp) {
    float th[W], dn[W];
#pragma unroll
    for (int j = 0; j < W; j++) {
        const ulonglong2* row = reinterpret_cast<const ulonglong2*>(sw + j * RS);
        u64 av = sbp[j];                 // (b, 0)
        u64 ad = pack2(0.0f, 0.0f);
#pragma unroll
        for (int kk = 0; kk < KP / 2; kk++) {
            ulonglong2 wp = row[kk];
            av = ffma2(hv[2 * kk + 0], wp.x, av);
            ad = ffma2(dv[2 * kk + 0], wp.x, ad);
            av = ffma2(hv[2 * kk + 1], wp.y, av);
            ad = ffma2(dv[2 * kk + 1], wp.y, ad);
        }
        float lo, hi, dlo, dhi;
        unpack2(av, lo, hi);
        unpack2(ad, dlo, dhi);
        float z = lo + hi;
        float dpre = dlo + dhi;
        float t2 = fast_tanh(z);
        th[j] = t2;
        dn[j] = fmaf(-t2, t2 * dpre, dpre);   // (1-th^2)*dpre
    }
#pragma unroll
    for (int jj = 0; jj < KP; jj++) {
        hv[jj] = pack2(th[2 * jj], th[2 * jj + 1]);
        dv[jj] = pack2(dn[2 * jj], dn[2 * jj + 1]);
    }
}

__global__ __launch_bounds__(256)
void lorenz_pinn_kernel(const float* __restrict__ t,
                        const float* __restrict__ W1, const float* __restrict__ b1,
                        const float* __restrict__ W2, const float* __restrict__ b2,
                        const float* __restrict__ W3, const float* __restrict__ b3,
                        const float* __restrict__ W4, const float* __restrict__ b4,
                        const float* __restrict__ Wo, const float* __restrict__ bo,
                        const float* __restrict__ c1p, const float* __restrict__ c2p,
                        const float* __restrict__ c3p,
                        float* __restrict__ out, int n) {
    // Each weight row j holds KP pairs (w[2kk][j], w[2kk+1][j]), padded to RS u64.
    __shared__ __align__(16) u64 sW2[W * RS];
    __shared__ __align__(16) u64 sW3[W * RS];
    __shared__ __align__(16) u64 sW4[W * RS];
    __shared__ __align__(16) u64 sWo[3 * RS];
    __shared__ u64 sb2p[W], sb3p[W], sb4p[W];
    __shared__ float sW1[W], sb1[W], sbo[4];

    for (int idx = threadIdx.x; idx < W * KP; idx += blockDim.x) {
        int j = idx / KP, kk = idx % KP;
        int s = j * RS + kk;
        sW2[s] = pack2(W2[(2 * kk) * W + j], W2[(2 * kk + 1) * W + j]);
        sW3[s] = pack2(W3[(2 * kk) * W + j], W3[(2 * kk + 1) * W + j]);
        sW4[s] = pack2(W4[(2 * kk) * W + j], W4[(2 * kk + 1) * W + j]);
    }
    if (threadIdx.x < 3 * KP) {
        int c = threadIdx.x / KP, kk = threadIdx.x % KP;
        sWo[c * RS + kk] = pack2(Wo[(2 * kk) * 3 + c], Wo[(2 * kk + 1) * 3 + c]);
    }
    if (threadIdx.x < W) {
        sW1[threadIdx.x] = W1[threadIdx.x];
        sb1[threadIdx.x] = b1[threadIdx.x];
        sb2p[threadIdx.x] = pack2(b2[threadIdx.x], 0.0f);
        sb3p[threadIdx.x] = pack2(b3[threadIdx.x], 0.0f);
        sb4p[threadIdx.x] = pack2(b4[threadIdx.x], 0.0f);
    }
    if (threadIdx.x < 3) sbo[threadIdx.x] = bo[threadIdx.x];
    __syncthreads();

    int i = blockIdx.x * blockDim.x + threadIdx.x;
    if (i >= n) return;

    float tv = t[i];
    float C1 = __ldg(c1p), C2 = __ldg(c2p), C3 = __ldg(c3p);

    // Layer 1: pre = t*W1 + b1, dpre = W1 (tangent of t is 1). Pack along k.
    u64 hv[KP], dv[KP];
    {
        float th[W], dn[W];
#pragma unroll
        for (int j = 0; j < W; j++) {
            float w = sW1[j];
            float t2 = fast_tanh(fmaf(tv, w, sb1[j]));
            th[j] = t2;
            dn[j] = fmaf(-t2, t2 * w, w);
        }
#pragma unroll
        for (int jj = 0; jj < KP; jj++) {
            hv[jj] = pack2(th[2 * jj], th[2 * jj + 1]);
            dv[jj] = pack2(dn[2 * jj], dn[2 * jj + 1]);
        }
    }

    layer(hv, dv, sW2, sb2p);
    layer(hv, dv, sW3, sb3p);
    layer(hv, dv, sW4, sb4p);

    // Output head (3 units, no activation).
    float o[3], d[3];
#pragma unroll
    for (int c = 0; c < 3; c++) {
        const ulonglong2* row = reinterpret_cast<const ulonglong2*>(sWo + c * RS);
        u64 av = pack2(sbo[c], 0.0f);
        u64 ad = pack2(0.0f, 0.0f);
#pragma unroll
        for (int kk = 0; kk < KP / 2; kk++) {
            ulonglong2 wp = row[kk];
            av = ffma2(hv[2 * kk + 0], wp.x, av);
            ad = ffma2(dv[2 * kk + 0], wp.x, ad);
            av = ffma2(hv[2 * kk + 1], wp.y, av);
            ad = ffma2(dv[2 * kk + 1], wp.y, ad);
        }
        float lo, hi, dlo, dhi;
        unpack2(av, lo, hi);
        unpack2(ad, dlo, dhi);
        o[c] = lo + hi;
        d[c] = dlo + dhi;
    }

    float x = o[0], y = o[1], z = o[2];
    float fx = d[0] - C1 * (y - x);
    float fy = d[1] - x * (C2 - z) + y;
    float fz = d[2] - x * y + C3 * z;

    float* po = out + (size_t)i * 6;
    po[0] = x; po[1] = y; po[2] = z;
    po[3] = fx; po[4] = fy; po[5] = fz;
}

extern "C" void kernel_launch(void* const* d_in, const int* in_sizes, int n_in,
                              void* d_out, int out_size) {
    const float* t  = (const float*)d_in[0];
    const float* W1 = (const float*)d_in[1];
    const float* b1 = (const float*)d_in[2];
    const float* W2 = (const float*)d_in[3];
    const float* b2 = (const float*)d_in[4];
    const float* W3 = (const float*)d_in[5];
    const float* b3 = (const float*)d_in[6];
    const float* W4 = (const float*)d_in[7];
    const float* b4 = (const float*)d_in[8];
    const float* Wo = (const float*)d_in[9];
    const float* bo = (const float*)d_in[10];
    const float* c1 = (const float*)d_in[11];
    const float* c2 = (const float*)d_in[12];
    const float* c3 = (const float*)d_in[13];
    float* out = (float*)d_out;
    int n = in_sizes[0];
    int blocks = (n + 255) / 256;
    lorenz_pinn_kernel<<<blocks, 256>>>(t, W1, b1, W2, b2, W3, b3, W4, b4,
                                        Wo, bo, c1, c2, c3, out, n);
}

// round 7
// speedup vs baseline: 1.1904x; 1.0244x over previous
#include <cuda_runtime.h>

// LorenzPINN: per-row forward + JVP of a 1->20->20->20->20->3 tanh MLP + Lorenz
// residuals. fp32, f32x2 packed along K (R4 layout, 4B/weight in smem).
// R5: pair-j units -> 4 independent FFMA2 chains per iteration; ping-pong
//     layer buffers (no copy); paired biases; launch_bounds(256,2) so ptxas
//     uses the full 128-reg budget for load hoisting. (R4 was latency-bound:
//     fma 60%, issue 55%, both pipes idle ~40%.)

#define W  20
#define KP 10          // k-pairs (and j-pairs) per layer
typedef unsigned long long u64;

__device__ __forceinline__ u64 pack2(float lo, float hi) {
    u64 r; asm("mov.b64 %0,{%1,%2};" : "=l"(r) : "f"(lo), "f"(hi)); return r;
}
__device__ __forceinline__ void unpack2(u64 v, float& lo, float& hi) {
    asm("mov.b64 {%0,%1},%2;" : "=f"(lo), "=f"(hi) : "l"(v));
}
__device__ __forceinline__ u64 ffma2(u64 a, u64 b, u64 c) {
    u64 d; asm("fma.rn.f32x2 %0,%1,%2,%3;" : "=l"(d) : "l"(a), "l"(b), "l"(c)); return d;
}

// tanh(x) = 1 - 2/(e^{2x}+1) via MUFU EX2 + RCP. Saturates correctly at +-inf.
__device__ __forceinline__ float fast_tanh(float x) {
    float e;
    asm("ex2.approx.f32 %0, %1;" : "=f"(e) : "f"(x * 2.885390081777927f)); // 2*log2(e)
    float r;
    asm("rcp.approx.f32 %0, %1;" : "=f"(r) : "f"(e + 1.0f));
    return fmaf(-2.0f, r, 1.0f);
}

// One hidden layer, pair-j form. Inputs ih/id (packed along k), outputs oh/od.
// sw[jj*KP+kk] = { (W[2kk][2jj],W[2kk+1][2jj]) , (W[2kk][2jj+1],W[2kk+1][2jj+1]) }
// sbp[jj] = (b[2jj], b[2jj+1]).
__device__ __forceinline__ void layerP(const u64 (&ih)[KP], const u64 (&id)[KP],
                                       u64 (&oh)[KP], u64 (&od)[KP],
                                       const ulonglong2* __restrict__ sw,
                                       const u64* __restrict__ sbp) {
#pragma unroll
    for (int jj = 0; jj < KP; jj++) {
        float b0, b1; unpack2(sbp[jj], b0, b1);
        u64 av0 = pack2(b0, 0.0f), ad0 = pack2(0.0f, 0.0f);
        u64 av1 = pack2(b1, 0.0f), ad1 = pack2(0.0f, 0.0f);
        const ulonglong2* row = sw + jj * KP;
#pragma unroll
        for (int kk = 0; kk < KP; kk++) {
            ulonglong2 wp = row[kk];            // one LDS.128 feeds 4 FFMA2
            av0 = ffma2(ih[kk], wp.x, av0);
            ad0 = ffma2(id[kk], wp.x, ad0);
            av1 = ffma2(ih[kk], wp.y, av1);
            ad1 = ffma2(id[kk], wp.y, ad1);
        }
        float lo, hi, dlo, dhi, z0, z1, dp0, dp1;
        unpack2(av0, lo, hi);  z0  = lo + hi;
        unpack2(ad0, dlo, dhi); dp0 = dlo + dhi;
        unpack2(av1, lo, hi);  z1  = lo + hi;
        unpack2(ad1, dlo, dhi); dp1 = dlo + dhi;
        float t0 = fast_tanh(z0);
        float t1 = fast_tanh(z1);
        oh[jj] = pack2(t0, t1);
        od[jj] = pack2(fmaf(-t0, t0 * dp0, dp0), fmaf(-t1, t1 * dp1, dp1));
    }
}

__global__ __launch_bounds__(256, 2)
void lorenz_pinn_kernel(const float* __restrict__ t,
                        const float* __restrict__ W1, const float* __restrict__ b1,
                        const float* __restrict__ W2, const float* __restrict__ b2,
                        const float* __restrict__ W3, const float* __restrict__ b3,
                        const float* __restrict__ W4, const float* __restrict__ b4,
                        const float* __restrict__ Wo, const float* __restrict__ bo,
                        const float* __restrict__ c1p, const float* __restrict__ c2p,
                        const float* __restrict__ c3p,
                        float* __restrict__ out, int n) {
    __shared__ __align__(16) ulonglong2 sW2[KP * KP];
    __shared__ __align__(16) ulonglong2 sW3[KP * KP];
    __shared__ __align__(16) ulonglong2 sW4[KP * KP];
    __shared__ u64 sWo[3 * KP];
    __shared__ u64 sb2p[KP], sb3p[KP], sb4p[KP];
    __shared__ float sW1[W], sb1[W], sbo[4];

    // Stage weights: sw[jj*KP+kk].x = pair for unit 2jj, .y = pair for 2jj+1.
    for (int idx = threadIdx.x; idx < KP * KP; idx += blockDim.x) {
        int jj = idx / KP, kk = idx % KP;
        int k0 = 2 * kk, k1 = 2 * kk + 1, j0 = 2 * jj, j1 = 2 * jj + 1;
        sW2[idx] = make_ulonglong2(pack2(W2[k0 * W + j0], W2[k1 * W + j0]),
                                   pack2(W2[k0 * W + j1], W2[k1 * W + j1]));
        sW3[idx] = make_ulonglong2(pack2(W3[k0 * W + j0], W3[k1 * W + j0]),
                                   pack2(W3[k0 * W + j1], W3[k1 * W + j1]));
        sW4[idx] = make_ulonglong2(pack2(W4[k0 * W + j0], W4[k1 * W + j0]),
                                   pack2(W4[k0 * W + j1], W4[k1 * W + j1]));
    }
    if (threadIdx.x < 3 * KP) {
        int c = threadIdx.x / KP, kk = threadIdx.x % KP;
        sWo[threadIdx.x] = pack2(Wo[(2 * kk) * 3 + c], Wo[(2 * kk + 1) * 3 + c]);
    }
    if (threadIdx.x < KP) {
        int jj = threadIdx.x;
        sb2p[jj] = pack2(b2[2 * jj], b2[2 * jj + 1]);
        sb3p[jj] = pack2(b3[2 * jj], b3[2 * jj + 1]);
        sb4p[jj] = pack2(b4[2 * jj], b4[2 * jj + 1]);
    }
    if (threadIdx.x < W) {
        sW1[threadIdx.x] = W1[threadIdx.x];
        sb1[threadIdx.x] = b1[threadIdx.x];
    }
    if (threadIdx.x < 3) sbo[threadIdx.x] = bo[threadIdx.x];
    __syncthreads();

    int i = blockIdx.x * blockDim.x + threadIdx.x;
    if (i >= n) return;

    float tv = t[i];
    float C1 = __ldg(c1p), C2 = __ldg(c2p), C3 = __ldg(c3p);

    // Layer 1: pre = t*W1 + b1, dpre = W1 (tangent of t is 1). Packed along k.
    u64 hA[KP], dA[KP], hB[KP], dB[KP];
#pragma unroll
    for (int jj = 0; jj < KP; jj++) {
        float w0 = sW1[2 * jj], w1 = sW1[2 * jj + 1];
        float t0 = fast_tanh(fmaf(tv, w0, sb1[2 * jj]));
        float t1 = fast_tanh(fmaf(tv, w1, sb1[2 * jj + 1]));
        hA[jj] = pack2(t0, t1);
        dA[jj] = pack2(fmaf(-t0, t0 * w0, w0), fmaf(-t1, t1 * w1, w1));
    }

    layerP(hA, dA, hB, dB, sW2, sb2p);   // L2: A -> B
    layerP(hB, dB, hA, dA, sW3, sb3p);   // L3: B -> A
    layerP(hA, dA, hB, dB, sW4, sb4p);   // L4: A -> B

    // Output head (3 units, no activation) from buffer B.
    float o[3], d[3];
#pragma unroll
    for (int c = 0; c < 3; c++) {
        u64 av = pack2(sbo[c], 0.0f);
        u64 ad = pack2(0.0f, 0.0f);
#pragma unroll
        for (int kk = 0; kk < KP; kk++) {
            u64 wp = sWo[c * KP + kk];
            av = ffma2(hB[kk], wp, av);
            ad = ffma2(dB[kk], wp, ad);
        }
        float lo, hi, dlo, dhi;
        unpack2(av, lo, hi);   o[c] = lo + hi;
        unpack2(ad, dlo, dhi); d[c] = dlo + dhi;
    }

    float x = o[0], y = o[1], z = o[2];
    float fx = d[0] - C1 * (y - x);
    float fy = d[1] - x * (C2 - z) + y;
    float fz = d[2] - x * y + C3 * z;

    float* po = out + (size_t)i * 6;
    po[0] = x; po[1] = y; po[2] = z;
    po[3] = fx; po[4] = fy; po[5] = fz;
}

extern "C" void kernel_launch(void* const* d_in, const int* in_sizes, int n_in,
                              void* d_out, int out_size) {
    const float* t  = (const float*)d_in[0];
    const float* W1 = (const float*)d_in[1];
    const float* b1 = (const float*)d_in[2];
    const float* W2 = (const float*)d_in[3];
    const float* b2 = (const float*)d_in[4];
    const float* W3 = (const float*)d_in[5];
    const float* b3 = (const float*)d_in[6];
    const float* W4 = (const float*)d_in[7];
    const float* b4 = (const float*)d_in[8];
    const float* Wo = (const float*)d_in[9];
    const float* bo = (const float*)d_in[10];
    const float* c1 = (const float*)d_in[11];
    const float* c2 = (const float*)d_in[12];
    const float* c3 = (const float*)d_in[13];
    float* out = (float*)d_out;
    int n = in_sizes[0];
    int blocks = (n + 255) / 256;
    lorenz_pinn_kernel<<<blocks, 256>>>(t, W1, b1, W2, b2, W3, b3, W4, b4,
                                        Wo, bo, c1, c2, c3, out, n);
}

// round 8
// speedup vs baseline: 1.3098x; 1.1003x over previous
#include <cuda_runtime.h>

// LorenzPINN: per-row forward + JVP of a 1->20->20->20->20->3 tanh MLP + Lorenz
// residuals. fp32.
// R6: TRANSPOSED accumulation — pack f32x2 along output units j, broadcast the
//     scalar input h_k/dh_k (dup'd). Removes all horizontal FADDs and the
//     ping-pong buffer; 20 independent FFMA2 chains; in-place state;
//     launch_bounds(192,3) for 18 warps/SM. Weights stay 4B/weight in smem.

#define W  20
#define JP 10          // j-pairs per layer
typedef unsigned long long u64;

__device__ __forceinline__ u64 pack2(float lo, float hi) {
    u64 r; asm("mov.b64 %0,{%1,%2};" : "=l"(r) : "f"(lo), "f"(hi)); return r;
}
__device__ __forceinline__ u64 dup2(float x) {
    u64 r; asm("mov.b64 %0,{%1,%1};" : "=l"(r) : "f"(x)); return r;
}
__device__ __forceinline__ void unpack2(u64 v, float& lo, float& hi) {
    asm("mov.b64 {%0,%1},%2;" : "=f"(lo), "=f"(hi) : "l"(v));
}
__device__ __forceinline__ u64 ffma2(u64 a, u64 b, u64 c) {
    u64 d; asm("fma.rn.f32x2 %0,%1,%2,%3;" : "=l"(d) : "l"(a), "l"(b), "l"(c)); return d;
}

// tanh(x) = 1 - 2/(e^{2x}+1) via MUFU EX2 + RCP. Saturates correctly at +-inf.
__device__ __forceinline__ float fast_tanh(float x) {
    float e;
    asm("ex2.approx.f32 %0, %1;" : "=f"(e) : "f"(x * 2.885390081777927f)); // 2*log2(e)
    float r;
    asm("rcp.approx.f32 %0, %1;" : "=f"(r) : "f"(e + 1.0f));
    return fmaf(-2.0f, r, 1.0f);
}

// One hidden layer, transposed. State th/td updated IN PLACE.
// sw[k*JP+jj] = (W[k][2jj], W[k][2jj+1]); sbp[jj] = (b[2jj], b[2jj+1]).
__device__ __forceinline__ void layerT(float (&th)[W], float (&td)[W],
                                       const u64* __restrict__ sw,
                                       const u64* __restrict__ sbp) {
    u64 av[JP], ad[JP];
#pragma unroll
    for (int jj = 0; jj < JP; jj++) { av[jj] = sbp[jj]; ad[jj] = 0ULL; }
#pragma unroll
    for (int k = 0; k < W; k++) {
        u64 hk = dup2(th[k]);
        u64 dk = dup2(td[k]);
        const ulonglong2* rowk = reinterpret_cast<const ulonglong2*>(sw + k * JP);
#pragma unroll
        for (int q = 0; q < JP / 2; q++) {
            ulonglong2 wp = rowk[q];        // one LDS.128 feeds 4 FFMA2
            av[2 * q + 0] = ffma2(hk, wp.x, av[2 * q + 0]);
            ad[2 * q + 0] = ffma2(dk, wp.x, ad[2 * q + 0]);
            av[2 * q + 1] = ffma2(hk, wp.y, av[2 * q + 1]);
            ad[2 * q + 1] = ffma2(dk, wp.y, ad[2 * q + 1]);
        }
    }
#pragma unroll
    for (int jj = 0; jj < JP; jj++) {
        float z0, z1, dp0, dp1;
        unpack2(av[jj], z0, z1);            // accumulators ARE (z_2jj, z_2jj+1)
        unpack2(ad[jj], dp0, dp1);
        float t0 = fast_tanh(z0);
        float t1 = fast_tanh(z1);
        th[2 * jj + 0] = t0;
        th[2 * jj + 1] = t1;
        td[2 * jj + 0] = fmaf(-t0, t0 * dp0, dp0);
        td[2 * jj + 1] = fmaf(-t1, t1 * dp1, dp1);
    }
}

__global__ __launch_bounds__(192, 3)
void lorenz_pinn_kernel(const float* __restrict__ t,
                        const float* __restrict__ W1, const float* __restrict__ b1,
                        const float* __restrict__ W2, const float* __restrict__ b2,
                        const float* __restrict__ W3, const float* __restrict__ b3,
                        const float* __restrict__ W4, const float* __restrict__ b4,
                        const float* __restrict__ Wo, const float* __restrict__ bo,
                        const float* __restrict__ c1p, const float* __restrict__ c2p,
                        const float* __restrict__ c3p,
                        float* __restrict__ out, int n) {
    __shared__ __align__(16) u64 sW2[W * JP];
    __shared__ __align__(16) u64 sW3[W * JP];
    __shared__ __align__(16) u64 sW4[W * JP];
    __shared__ __align__(16) u64 sWoD[3 * W];   // dup'd (w,w) head weights
    __shared__ u64 sb2p[JP], sb3p[JP], sb4p[JP];
    __shared__ float sW1[W], sb1[W], sbo[4];

    // sw[k*JP+jj] = (W[k][2jj], W[k][2jj+1])  (W stored row-major [k][j]).
    for (int idx = threadIdx.x; idx < W * JP; idx += blockDim.x) {
        int k = idx / JP, jj = idx % JP;
        int j0 = 2 * jj, j1 = 2 * jj + 1;
        sW2[idx] = pack2(W2[k * W + j0], W2[k * W + j1]);
        sW3[idx] = pack2(W3[k * W + j0], W3[k * W + j1]);
        sW4[idx] = pack2(W4[k * W + j0], W4[k * W + j1]);
    }
    if (threadIdx.x < 3 * W) {
        int c = threadIdx.x / W, k = threadIdx.x % W;
        float w = Wo[k * 3 + c];
        sWoD[c * W + k] = pack2(w, w);
    }
    if (threadIdx.x < JP) {
        int jj = threadIdx.x;
        sb2p[jj] = pack2(b2[2 * jj], b2[2 * jj + 1]);
        sb3p[jj] = pack2(b3[2 * jj], b3[2 * jj + 1]);
        sb4p[jj] = pack2(b4[2 * jj], b4[2 * jj + 1]);
    }
    if (threadIdx.x < W) {
        sW1[threadIdx.x] = W1[threadIdx.x];
        sb1[threadIdx.x] = b1[threadIdx.x];
    }
    if (threadIdx.x < 3) sbo[threadIdx.x] = bo[threadIdx.x];
    __syncthreads();

    int i = blockIdx.x * blockDim.x + threadIdx.x;
    if (i >= n) return;

    float tv = t[i];
    float C1 = __ldg(c1p), C2 = __ldg(c2p), C3 = __ldg(c3p);

    // Layer 1: pre = t*W1 + b1, dpre = W1 (tangent of t is 1). Scalar state.
    float th[W], td[W];
#pragma unroll
    for (int j = 0; j < W; j++) {
        float w = sW1[j];
        float t0 = fast_tanh(fmaf(tv, w, sb1[j]));
        th[j] = t0;
        td[j] = fmaf(-t0, t0 * w, w);
    }

    layerT(th, td, sW2, sb2p);
    layerT(th, td, sW3, sb3p);
    layerT(th, td, sW4, sb4p);

    // Output head: pack (value, tangent) per k; dup'd weights -> acc = (o_c, d_c).
    u64 hd[W];
#pragma unroll
    for (int k = 0; k < W; k++) hd[k] = pack2(th[k], td[k]);

    float o[3], d[3];
#pragma unroll
    for (int c = 0; c < 3; c++) {
        u64 acc = pack2(sbo[c], 0.0f);
        const ulonglong2* row = reinterpret_cast<const ulonglong2*>(sWoD + c * W);
#pragma unroll
        for (int q = 0; q < W / 2; q++) {
            ulonglong2 wp = row[q];
            acc = ffma2(hd[2 * q + 0], wp.x, acc);
            acc = ffma2(hd[2 * q + 1], wp.y, acc);
        }
        unpack2(acc, o[c], d[c]);
    }

    float x = o[0], y = o[1], z = o[2];
    float fx = d[0] - C1 * (y - x);
    float fy = d[1] - x * (C2 - z) + y;
    float fz = d[2] - x * y + C3 * z;

    float2* po = reinterpret_cast<float2*>(out + (size_t)i * 6);
    po[0] = make_float2(x, y);
    po[1] = make_float2(z, fx);
    po[2] = make_float2(fy, fz);
}

extern "C" void kernel_launch(void* const* d_in, const int* in_sizes, int n_in,
                              void* d_out, int out_size) {
    const float* t  = (const float*)d_in[0];
    const float* W1 = (const float*)d_in[1];
    const float* b1 = (const float*)d_in[2];
    const float* W2 = (const float*)d_in[3];
    const float* b2 = (const float*)d_in[4];
    const float* W3 = (const float*)d_in[5];
    const float* b3 = (const float*)d_in[6];
    const float* W4 = (const float*)d_in[7];
    const float* b4 = (const float*)d_in[8];
    const float* Wo = (const float*)d_in[9];
    const float* bo = (const float*)d_in[10];
    const float* c1 = (const float*)d_in[11];
    const float* c2 = (const float*)d_in[12];
    const float* c3 = (const float*)d_in[13];
    float* out = (float*)d_out;
    int n = in_sizes[0];
    int blocks = (n + 191) / 192;
    lorenz_pinn_kernel<<<blocks, 192>>>(t, W1, b1, W2, b2, W3, b3, W4, b4,
                                        Wo, bo, c1, c2, c3, out, n);
}